// round 15
// baseline (speedup 1.0000x reference)
#include <cuda_runtime.h>
#include <cuda_fp16.h>
#include <cstdint>
#include <math.h>

#define TOK   200704
#define CDIM  384
#define NHEAD 12
#define DHEAD 32
#define NWIN  4096
#define NPOS  49
#define HID   1536

// ---------------- static scratch ----------------------------------------------
__device__ __half g_xw [(size_t)TOK * CDIM];
__device__ __half g_qkv[(size_t)TOK * 3 * CDIM];
__device__ __half g_att[(size_t)TOK * CDIM];
__device__ float  g_x2 [(size_t)TOK * CDIM];
__device__ __half g_xn2[(size_t)TOK * CDIM];
__device__ __half g_h1 [(size_t)TOK * HID];
__device__ __half g_wqkv [CDIM * 3 * CDIM];
__device__ __half g_wproj[CDIM * CDIM];
__device__ __half g_wm1  [CDIM * HID];
__device__ __half g_wm2  [HID * CDIM];

// ---------------- helpers -------------------------------------------------------
__device__ __forceinline__ uint32_t smem_u32(const void* p) {
    uint32_t a;
    asm("{ .reg .u64 t; cvta.to.shared.u64 t, %1; cvt.u32.u64 %0, t; }" : "=r"(a) : "l"(p));
    return a;
}
__device__ __forceinline__ void cp16(uint32_t dst, const void* src) {
    asm volatile("cp.async.cg.shared.global [%0], [%1], 16;" :: "r"(dst), "l"(src));
}
#define CP_COMMIT() asm volatile("cp.async.commit_group;" ::: "memory")
#define CP_WAIT(n)  asm volatile("cp.async.wait_group %0;" :: "n"(n) : "memory")

__device__ __forceinline__ void ldsm4(uint32_t* r, uint32_t addr) {
    asm volatile("ldmatrix.sync.aligned.m8n8.x4.shared.b16 {%0,%1,%2,%3}, [%4];"
                 : "=r"(r[0]), "=r"(r[1]), "=r"(r[2]), "=r"(r[3]) : "r"(addr));
}
__device__ __forceinline__ void ldsm4t(uint32_t* r, uint32_t addr) {
    asm volatile("ldmatrix.sync.aligned.m8n8.x4.trans.shared.b16 {%0,%1,%2,%3}, [%4];"
                 : "=r"(r[0]), "=r"(r[1]), "=r"(r[2]), "=r"(r[3]) : "r"(addr));
}
// f16 inputs, f16 accumulators (2 regs)
__device__ __forceinline__ void mma_h16(uint32_t* c, const uint32_t* a, const uint32_t* b) {
    asm volatile("mma.sync.aligned.m16n8k16.row.col.f16.f16.f16.f16 "
                 "{%0,%1}, {%2,%3,%4,%5}, {%6,%7}, {%0,%1};"
                 : "+r"(c[0]), "+r"(c[1])
                 : "r"(a[0]), "r"(a[1]), "r"(a[2]), "r"(a[3]), "r"(b[0]), "r"(b[1]));
}
// f16 inputs, f32 accumulators (attention)
__device__ __forceinline__ void mma_h32(float* c, const uint32_t* a, const uint32_t* b) {
    asm volatile("mma.sync.aligned.m16n8k16.row.col.f32.f16.f16.f32 "
                 "{%0,%1,%2,%3}, {%4,%5,%6,%7}, {%8,%9}, {%0,%1,%2,%3};"
                 : "+f"(c[0]), "+f"(c[1]), "+f"(c[2]), "+f"(c[3])
                 : "r"(a[0]), "r"(a[1]), "r"(a[2]), "r"(a[3]), "r"(b[0]), "r"(b[1]));
}
__device__ __forceinline__ uint32_t pack_h2(float lo, float hi) {
    __half2 h = __floats2half2_rn(lo, hi);
    return *(uint32_t*)&h;
}

// ---------------- fused weight convert ------------------------------------------
#define WS0 (CDIM * 3 * CDIM)
#define WS1 (CDIM * CDIM)
#define WS2 (CDIM * HID)
#define WS3 (HID * CDIM)
__global__ void wconv_all(const float* __restrict__ w0, const float* __restrict__ w1,
                          const float* __restrict__ w2, const float* __restrict__ w3,
                          __half* __restrict__ d0, __half* __restrict__ d1,
                          __half* __restrict__ d2, __half* __restrict__ d3) {
    int i = blockIdx.x * 256 + threadIdx.x;
    if (i < WS0) { d0[i] = __float2half(w0[i]); return; }
    i -= WS0;
    if (i < WS1) { d1[i] = __float2half(w1[i]); return; }
    i -= WS1;
    if (i < WS2) { d2[i] = __float2half(w2[i]); return; }
    i -= WS2;
    if (i < WS3) { d3[i] = __float2half(w3[i]); }
}

// ---------------- LayerNorm: warp-per-token, float4, shuffle-only reduce --------
template <bool REMAP>
__global__ void __launch_bounds__(256)
ln_kernel(const float* __restrict__ xin,
          const float* __restrict__ sc,
          const float* __restrict__ bi,
          __half* __restrict__ xout) {
    int t = blockIdx.x * 8 + (threadIdx.x >> 5);
    int lane = threadIdx.x & 31;
    size_t src;
    if (REMAP) {
        int win = t / NPOS, npos = t - win * NPOS;
        int b = win >> 6, wy = (win >> 3) & 7, wx = win & 7;
        int py = npos / 7, px = npos - py * 7;
        int sy = wy * 7 + py + 3; if (sy >= 56) sy -= 56;
        int sx = wx * 7 + px + 3; if (sx >= 56) sx -= 56;
        src = (size_t)b * 3136 + sy * 56 + sx;
    } else src = (size_t)t;

    const float4* xp = (const float4*)(xin + src * CDIM);
    float4 v[3];
    float s = 0.f, s2 = 0.f;
#pragma unroll
    for (int i = 0; i < 3; ++i) {
        v[i] = xp[lane + 32 * i];
        s  += v[i].x + v[i].y + v[i].z + v[i].w;
        s2 += v[i].x * v[i].x + v[i].y * v[i].y + v[i].z * v[i].z + v[i].w * v[i].w;
    }
#pragma unroll
    for (int o = 16; o > 0; o >>= 1) {
        s  += __shfl_xor_sync(0xffffffffu, s,  o);
        s2 += __shfl_xor_sync(0xffffffffu, s2, o);
    }
    float mu  = s * (1.0f / CDIM);
    float var = s2 * (1.0f / CDIM) - mu * mu;
    float r = rsqrtf(var + 1e-6f);

    __half* op = xout + (size_t)t * CDIM;
#pragma unroll
    for (int i = 0; i < 3; ++i) {
        int idx = (lane + 32 * i) * 4;
        float4 g = *(const float4*)(sc + idx);
        float4 b4 = *(const float4*)(bi + idx);
        float o0 = (v[i].x - mu) * r * g.x + b4.x;
        float o1 = (v[i].y - mu) * r * g.y + b4.y;
        float o2 = (v[i].z - mu) * r * g.z + b4.z;
        float o3 = (v[i].w - mu) * r * g.w + b4.w;
        uint2 pk;
        pk.x = pack_h2(o0, o1);
        pk.y = pack_h2(o2, o3);
        *(uint2*)(op + idx) = pk;
    }
}

// ---------------- HMMA windowed attention: 4 warps/CTA, 1 m-tile/warp -----------
__global__ void __launch_bounds__(128)
attn_mma(const __half* __restrict__ qkv, __half* __restrict__ out) {
    int blk = blockIdx.x;
    int win = blk / NHEAD, head = blk - win * NHEAD;
    int wy = (win >> 3) & 7, wx = win & 7;

    __shared__ __align__(16) __half Ks[64 * 40];
    __shared__ __align__(16) __half Vs[64 * 40];
    __shared__ int rg[64];

    const int tid = threadIdx.x;
    const int lane = tid & 31, warp = tid >> 5;
    const __half* base  = qkv + (size_t)win * NPOS * (3 * CDIM);
    const __half* qhead = base + head * DHEAD;

#pragma unroll
    for (int i = tid; i < 15 * 20; i += 128) {
        int r = 49 + i / 20, c = i % 20;
        ((float*)Ks)[r * 20 + c] = 0.f;
        ((float*)Vs)[r * 20 + c] = 0.f;
    }
    for (int u = tid; u < 196; u += 128) {
        int r = u >> 2, cc = u & 3;
        const __half* rp = base + (size_t)r * (3 * CDIM) + head * DHEAD + cc * 8;
        *(uint4*)(Ks + r * 40 + cc * 8) = *(const uint4*)(rp + CDIM);
        *(uint4*)(Vs + r * 40 + cc * 8) = *(const uint4*)(rp + 2 * CDIM);
    }
    for (int p = tid; p < NPOS; p += 128) {
        int py = p / 7, px = p - py * 7;
        int hy = wy * 7 + py, hx = wx * 7 + px;
        int cy = hy < 49 ? 0 : (hy < 53 ? 1 : 2);
        int cx = hx < 49 ? 0 : (hx < 53 ? 1 : 2);
        rg[p] = cy * 3 + cx;
    }
    __syncthreads();

    const uint32_t kb = smem_u32(Ks), vb = smem_u32(Vs);
    const float scale = 0.17677669529663687f;

    int  rk[7][2];
    bool kv_ok[7][2];
#pragma unroll
    for (int nt = 0; nt < 7; ++nt)
#pragma unroll
        for (int c = 0; c < 2; ++c) {
            int k = 8 * nt + 2 * (lane & 3) + c;
            kv_ok[nt][c] = (k < 49);
            rk[nt][c] = rg[k < 49 ? k : 0];
        }

    const int mt = warp;
    int r0 = mt * 16 + (lane >> 2), r1 = r0 + 8;
    bool ok0 = r0 < NPOS, ok1 = r1 < NPOS;
    const __half* q0p = qhead + (size_t)r0 * (3 * CDIM);
    const __half* q1p = qhead + (size_t)r1 * (3 * CDIM);
    uint32_t afr[2][4];
#pragma unroll
    for (int kk = 0; kk < 2; ++kk) {
        int c0 = kk * 16 + (lane & 3) * 2, c1 = c0 + 8;
        afr[kk][0] = ok0 ? *(const uint32_t*)(q0p + c0) : 0u;
        afr[kk][1] = ok1 ? *(const uint32_t*)(q1p + c0) : 0u;
        afr[kk][2] = ok0 ? *(const uint32_t*)(q0p + c1) : 0u;
        afr[kk][3] = ok1 ? *(const uint32_t*)(q1p + c1) : 0u;
    }

    float sc[7][4];
#pragma unroll
    for (int nt = 0; nt < 7; ++nt)
#pragma unroll
        for (int r = 0; r < 4; ++r) sc[nt][r] = 0.f;

#pragma unroll
    for (int kk = 0; kk < 2; ++kk) {
#pragma unroll
        for (int np = 0; np < 4; ++np) {
            uint32_t t[4];
            ldsm4(t, kb + (np * 16 + (lane & 15)) * 80 + (lane >> 4) * 16 + kk * 32);
            uint32_t b0[2] = {t[0], t[2]};
            uint32_t b1[2] = {t[1], t[3]};
            mma_h32(sc[2 * np], afr[kk], b0);
            if (2 * np + 1 < 7) mma_h32(sc[2 * np + 1], afr[kk], b1);
        }
    }

    int rq0 = ok0 ? rg[r0] : -1;
    int rq1 = ok1 ? rg[r1] : -1;
    float mx0 = -1e30f, mx1 = -1e30f;
#pragma unroll
    for (int nt = 0; nt < 7; ++nt) {
#pragma unroll
        for (int r = 0; r < 4; ++r) {
            int half_ = r >> 1, c = r & 1;
            float s = sc[nt][r] * scale;
            if (!kv_ok[nt][c]) s = -1e30f;
            else if (rk[nt][c] != (half_ ? rq1 : rq0)) s -= 100.f;
            sc[nt][r] = s;
            if (half_ == 0) mx0 = fmaxf(mx0, s); else mx1 = fmaxf(mx1, s);
        }
    }
    mx0 = fmaxf(mx0, __shfl_xor_sync(~0u, mx0, 1));
    mx0 = fmaxf(mx0, __shfl_xor_sync(~0u, mx0, 2));
    mx1 = fmaxf(mx1, __shfl_xor_sync(~0u, mx1, 1));
    mx1 = fmaxf(mx1, __shfl_xor_sync(~0u, mx1, 2));
    float s0 = 0.f, s1 = 0.f;
    uint32_t pk[7][2];
#pragma unroll
    for (int nt = 0; nt < 7; ++nt) {
        float e0 = __expf(sc[nt][0] - mx0); s0 += e0;
        float e1 = __expf(sc[nt][1] - mx0); s0 += e1;
        float e2 = __expf(sc[nt][2] - mx1); s1 += e2;
        float e3 = __expf(sc[nt][3] - mx1); s1 += e3;
        pk[nt][0] = pack_h2(e0, e1);
        pk[nt][1] = pack_h2(e2, e3);
    }
    s0 += __shfl_xor_sync(~0u, s0, 1); s0 += __shfl_xor_sync(~0u, s0, 2);
    s1 += __shfl_xor_sync(~0u, s1, 1); s1 += __shfl_xor_sync(~0u, s1, 2);
    float inv0 = 1.f / s0, inv1 = 1.f / s1;

    float acc[4][4];
#pragma unroll
    for (int nt = 0; nt < 4; ++nt)
#pragma unroll
        for (int r = 0; r < 4; ++r) acc[nt][r] = 0.f;

#pragma unroll
    for (int kt = 0; kt < 4; ++kt) {
        uint32_t vbf[4][2];
#pragma unroll
        for (int np = 0; np < 2; ++np) {
            uint32_t t[4];
            ldsm4t(t, vb + (kt * 16 + (lane & 15)) * 80 + ((lane >> 4) * 8 + np * 16) * 2);
            vbf[2 * np][0] = t[0]; vbf[2 * np][1] = t[1];
            vbf[2 * np + 1][0] = t[2]; vbf[2 * np + 1][1] = t[3];
        }
        uint32_t a[4];
        const int ta = 2 * kt, tb = 2 * kt + 1;
        a[0] = pk[ta][0]; a[1] = pk[ta][1];
        if (tb < 7) { a[2] = pk[tb][0]; a[3] = pk[tb][1]; }
        else        { a[2] = 0u;        a[3] = 0u; }
#pragma unroll
        for (int nt = 0; nt < 4; ++nt) mma_h32(acc[nt], a, vbf[nt]);
    }

#pragma unroll
    for (int half_ = 0; half_ < 2; ++half_) {
        int q = r0 + 8 * half_;
        if (q < NPOS) {
            __half* op = out + ((size_t)win * NPOS + q) * CDIM + head * DHEAD;
            float iv = half_ ? inv1 : inv0;
#pragma unroll
            for (int nt = 0; nt < 4; ++nt) {
                int d = nt * 8 + 2 * (lane & 3);
                *(uint32_t*)(op + d) = pack_h2(
                    acc[nt][2 * half_] * iv, acc[nt][2 * half_ + 1] * iv);
            }
        }
    }
}

// ---------------- HMMA fp16 GEMM (f16 accumulate): 128x128, BK=64, 2 CTA/SM -----
__device__ __forceinline__ float gelu_tanh(float v) {
    float u = 0.7978845608028654f * (v + 0.044715f * v * v * v);
    return 0.5f * v * (1.0f + tanhf(u));
}

#define ASTG 18432u
#define BSTG 17408u
#define SMEM_GEMM (2u * (ASTG + BSTG))

template <int EPI>
__global__ __launch_bounds__(256, 2)
void hgemm(const __half* __restrict__ A,
           const __half* __restrict__ Bw,
           const float* __restrict__ bias,
           void* __restrict__ CoutV,
           const float* __restrict__ res,
           int Nn, int K) {
    extern __shared__ char smraw[];
    const uint32_t a_base = smem_u32(smraw);
    const uint32_t b_base = a_base + 2u * ASTG;

    const int tid = threadIdx.x, lane = tid & 31, warp = tid >> 5;
    const int wm = warp & 3, wn = warp >> 2;
    const int bx = blockIdx.x, by = blockIdx.y;

    const __half* Ag = A  + (size_t)(by * 128) * K;
    const __half* Bg = Bw + bx * 128;

    auto load_stage = [&](int buf, int k0) {
        uint32_t a_s = a_base + buf * ASTG;
        uint32_t b_s = b_base + buf * BSTG;
#pragma unroll
        for (int j = 0; j < 4; ++j) {
            int id = tid + j * 256;
            int row = id >> 3, cc = id & 7;
            cp16(a_s + row * 144 + cc * 16, Ag + (size_t)row * K + k0 + cc * 8);
        }
#pragma unroll
        for (int j = 0; j < 4; ++j) {
            int id = tid + j * 256;
            int row = id >> 4, cc = id & 15;
            cp16(b_s + row * 272 + cc * 16, Bg + (size_t)(k0 + row) * Nn + cc * 8);
        }
        CP_COMMIT();
    };

    // f16 accumulators: 2 regs per (mi, ni) tile
    uint32_t acc[2][8][2];
#pragma unroll
    for (int i = 0; i < 2; ++i)
#pragma unroll
        for (int j = 0; j < 8; ++j) { acc[i][j][0] = 0u; acc[i][j][1] = 0u; }

    const int kIters = K >> 6;
    load_stage(0, 0);

    const uint32_t a_lm = a_base + (wm * 32 + (lane & 15)) * 144 + (lane >> 4) * 16;
    const uint32_t b_lm = b_base + (lane & 15) * 272 + (wn * 64 + (lane >> 4) * 8) * 2;

    for (int i = 0; i < kIters; ++i) {
        int cur = i & 1;
        if (i + 1 < kIters) { load_stage(1 - cur, (i + 1) * 64); CP_WAIT(1); }
        else CP_WAIT(0);
        __syncthreads();

        uint32_t aS = a_lm + cur * ASTG;
        uint32_t bS = b_lm + cur * BSTG;
#pragma unroll
        for (int kk = 0; kk < 4; ++kk) {
            uint32_t a[2][4];
#pragma unroll
            for (int mi = 0; mi < 2; ++mi)
                ldsm4(a[mi], aS + mi * 16 * 144 + kk * 32);
            uint32_t b[8][2];
#pragma unroll
            for (int nq = 0; nq < 4; ++nq) {
                uint32_t t[4];
                ldsm4t(t, bS + kk * 16 * 272 + nq * 32);
                b[2 * nq][0] = t[0]; b[2 * nq][1] = t[1];
                b[2 * nq + 1][0] = t[2]; b[2 * nq + 1][1] = t[3];
            }
#pragma unroll
            for (int mi = 0; mi < 2; ++mi)
#pragma unroll
                for (int ni = 0; ni < 8; ++ni)
                    mma_h16(acc[mi][ni], a[mi], b[ni]);
        }
        __syncthreads();
    }

    const int gid = lane >> 2, tig2 = (lane & 3) * 2;
#pragma unroll
    for (int mi = 0; mi < 2; ++mi) {
#pragma unroll
        for (int hf = 0; hf < 2; ++hf) {
            int m = by * 128 + wm * 32 + mi * 16 + gid + hf * 8;
            size_t orow_off; const float* rrow = nullptr;
            if (EPI == 2) {
                int win = m / NPOS, npos = m - win * NPOS;
                int b = win >> 6, wy = (win >> 3) & 7, wx = win & 7;
                int py = npos / 7, px = npos - py * 7;
                int yy = wy * 7 + py + 3; if (yy >= 56) yy -= 56;
                int xx = wx * 7 + px + 3; if (xx >= 56) xx -= 56;
                orow_off = ((size_t)b * 3136 + yy * 56 + xx) * (size_t)Nn;
                rrow = res + orow_off;
            } else {
                orow_off = (size_t)m * Nn;
                if (EPI == 3) rrow = res + orow_off;
            }
#pragma unroll
            for (int ni = 0; ni < 8; ++ni) {
                int n = bx * 128 + wn * 64 + ni * 8 + tig2;
                // unpack f16 accumulator reg hf: halves = (c_{2hf}, c_{2hf+1})
                float2 cv = __half22float2(*(__half2*)&acc[mi][ni][hf]);
                float v0 = cv.x + bias[n];
                float v1 = cv.y + bias[n + 1];
                if (EPI == 1) { v0 = gelu_tanh(v0); v1 = gelu_tanh(v1); }
                if (EPI == 0 || EPI == 1) {
                    *(uint32_t*)((__half*)CoutV + orow_off + n) = pack_h2(v0, v1);
                } else {
                    v0 += rrow[n]; v1 += rrow[n + 1];
                    *(float2*)((float*)CoutV + orow_off + n) = make_float2(v0, v1);
                }
            }
        }
    }
}

// ---------------- launch ----------------------------------------------------------
extern "C" void kernel_launch(void* const* d_in, const int* in_sizes, int n_in,
                              void* d_out, int out_size) {
    const float* x     = (const float*)d_in[0];
    const float* n1s   = (const float*)d_in[1];
    const float* n1b   = (const float*)d_in[2];
    const float* qkvw  = (const float*)d_in[3];
    const float* qkvb  = (const float*)d_in[4];
    const float* projw = (const float*)d_in[5];
    const float* projb = (const float*)d_in[6];
    const float* n2s   = (const float*)d_in[7];
    const float* n2b   = (const float*)d_in[8];
    const float* w1    = (const float*)d_in[9];
    const float* b1    = (const float*)d_in[10];
    const float* w2    = (const float*)d_in[11];
    const float* b2    = (const float*)d_in[12];
    float* out = (float*)d_out;

    __half *xw, *qkv, *att, *xn2, *h1, *wqkv, *wproj, *wm1, *wm2;
    float* x2;
    cudaGetSymbolAddress((void**)&xw,   g_xw);
    cudaGetSymbolAddress((void**)&qkv,  g_qkv);
    cudaGetSymbolAddress((void**)&att,  g_att);
    cudaGetSymbolAddress((void**)&x2,   g_x2);
    cudaGetSymbolAddress((void**)&xn2,  g_xn2);
    cudaGetSymbolAddress((void**)&h1,   g_h1);
    cudaGetSymbolAddress((void**)&wqkv, g_wqkv);
    cudaGetSymbolAddress((void**)&wproj,g_wproj);
    cudaGetSymbolAddress((void**)&wm1,  g_wm1);
    cudaGetSymbolAddress((void**)&wm2,  g_wm2);

    static bool attr_done = false;
    if (!attr_done) {
        cudaFuncSetAttribute(hgemm<0>, cudaFuncAttributeMaxDynamicSharedMemorySize, SMEM_GEMM);
        cudaFuncSetAttribute(hgemm<1>, cudaFuncAttributeMaxDynamicSharedMemorySize, SMEM_GEMM);
        cudaFuncSetAttribute(hgemm<2>, cudaFuncAttributeMaxDynamicSharedMemorySize, SMEM_GEMM);
        cudaFuncSetAttribute(hgemm<3>, cudaFuncAttributeMaxDynamicSharedMemorySize, SMEM_GEMM);
        attr_done = true;
    }

    const int wtot = WS0 + WS1 + WS2 + WS3;
    wconv_all<<<(wtot + 255) / 256, 256>>>(qkvw, projw, w1, w2, wqkv, wproj, wm1, wm2);

    ln_kernel<true><<<TOK / 8, 256>>>(x, n1s, n1b, xw);
    hgemm<0><<<dim3(1152 / 128, TOK / 128), 256, SMEM_GEMM>>>(xw, wqkv, qkvb, qkv, nullptr, 1152, CDIM);
    attn_mma<<<NWIN * NHEAD, 128>>>(qkv, att);
    hgemm<2><<<dim3(CDIM / 128, TOK / 128), 256, SMEM_GEMM>>>(att, wproj, projb, x2, x, CDIM, CDIM);
    ln_kernel<false><<<TOK / 8, 256>>>(x2, n2s, n2b, xn2);
    hgemm<1><<<dim3(HID / 128, TOK / 128), 256, SMEM_GEMM>>>(xn2, wm1, b1, h1, nullptr, HID, CDIM);
    hgemm<3><<<dim3(CDIM / 128, TOK / 128), 256, SMEM_GEMM>>>(h1, wm2, b2, out, x2, CDIM, HID);
}

// round 16
// speedup vs baseline: 1.0505x; 1.0505x over previous
#include <cuda_runtime.h>
#include <cuda_fp16.h>
#include <cstdint>
#include <math.h>

#define TOK   200704
#define CDIM  384
#define NHEAD 12
#define DHEAD 32
#define NWIN  4096
#define NPOS  49
#define HID   1536

// ---------------- static scratch ----------------------------------------------
__device__ __half g_xw [(size_t)TOK * CDIM];
__device__ __half g_qkv[(size_t)TOK * 3 * CDIM];
__device__ __half g_att[(size_t)TOK * CDIM];
__device__ __half g_x2 [(size_t)TOK * CDIM];        // residual stream, fp16
__device__ __half g_xn2[(size_t)TOK * CDIM];
__device__ __half g_h1 [(size_t)TOK * HID];
__device__ __half g_wqkv [CDIM * 3 * CDIM];
__device__ __half g_wproj[CDIM * CDIM];
__device__ __half g_wm1  [CDIM * HID];
__device__ __half g_wm2  [HID * CDIM];

// ---------------- helpers -------------------------------------------------------
__device__ __forceinline__ uint32_t smem_u32(const void* p) {
    uint32_t a;
    asm("{ .reg .u64 t; cvta.to.shared.u64 t, %1; cvt.u32.u64 %0, t; }" : "=r"(a) : "l"(p));
    return a;
}
__device__ __forceinline__ void cp16(uint32_t dst, const void* src) {
    asm volatile("cp.async.cg.shared.global [%0], [%1], 16;" :: "r"(dst), "l"(src));
}
#define CP_COMMIT() asm volatile("cp.async.commit_group;" ::: "memory")
#define CP_WAIT(n)  asm volatile("cp.async.wait_group %0;" :: "n"(n) : "memory")

__device__ __forceinline__ void ldsm4(uint32_t* r, uint32_t addr) {
    asm volatile("ldmatrix.sync.aligned.m8n8.x4.shared.b16 {%0,%1,%2,%3}, [%4];"
                 : "=r"(r[0]), "=r"(r[1]), "=r"(r[2]), "=r"(r[3]) : "r"(addr));
}
__device__ __forceinline__ void ldsm4t(uint32_t* r, uint32_t addr) {
    asm volatile("ldmatrix.sync.aligned.m8n8.x4.trans.shared.b16 {%0,%1,%2,%3}, [%4];"
                 : "=r"(r[0]), "=r"(r[1]), "=r"(r[2]), "=r"(r[3]) : "r"(addr));
}
// f16 inputs, f32 accumulators
__device__ __forceinline__ void mma_h32(float* c, const uint32_t* a, const uint32_t* b) {
    asm volatile("mma.sync.aligned.m16n8k16.row.col.f32.f16.f16.f32 "
                 "{%0,%1,%2,%3}, {%4,%5,%6,%7}, {%8,%9}, {%0,%1,%2,%3};"
                 : "+f"(c[0]), "+f"(c[1]), "+f"(c[2]), "+f"(c[3])
                 : "r"(a[0]), "r"(a[1]), "r"(a[2]), "r"(a[3]), "r"(b[0]), "r"(b[1]));
}
__device__ __forceinline__ uint32_t pack_h2(float lo, float hi) {
    __half2 h = __floats2half2_rn(lo, hi);
    return *(uint32_t*)&h;
}

// ---------------- fused weight convert ------------------------------------------
#define WS0 (CDIM * 3 * CDIM)
#define WS1 (CDIM * CDIM)
#define WS2 (CDIM * HID)
#define WS3 (HID * CDIM)
__global__ void wconv_all(const float* __restrict__ w0, const float* __restrict__ w1,
                          const float* __restrict__ w2, const float* __restrict__ w3,
                          __half* __restrict__ d0, __half* __restrict__ d1,
                          __half* __restrict__ d2, __half* __restrict__ d3) {
    int i = blockIdx.x * 256 + threadIdx.x;
    if (i < WS0) { d0[i] = __float2half(w0[i]); return; }
    i -= WS0;
    if (i < WS1) { d1[i] = __float2half(w1[i]); return; }
    i -= WS1;
    if (i < WS2) { d2[i] = __float2half(w2[i]); return; }
    i -= WS2;
    if (i < WS3) { d3[i] = __float2half(w3[i]); }
}

// ---------------- LN1: fp32 input + roll/window remap -> fp16 -------------------
__global__ void __launch_bounds__(256)
ln1_kernel(const float* __restrict__ xin,
           const float* __restrict__ sc,
           const float* __restrict__ bi,
           __half* __restrict__ xout) {
    int t = blockIdx.x * 8 + (threadIdx.x >> 5);
    int lane = threadIdx.x & 31;
    int win = t / NPOS, npos = t - win * NPOS;
    int b = win >> 6, wy = (win >> 3) & 7, wx = win & 7;
    int py = npos / 7, px = npos - py * 7;
    int sy = wy * 7 + py + 3; if (sy >= 56) sy -= 56;
    int sx = wx * 7 + px + 3; if (sx >= 56) sx -= 56;
    size_t src = (size_t)b * 3136 + sy * 56 + sx;

    const float4* xp = (const float4*)(xin + src * CDIM);
    float4 v[3];
    float s = 0.f, s2 = 0.f;
#pragma unroll
    for (int i = 0; i < 3; ++i) {
        v[i] = xp[lane + 32 * i];
        s  += v[i].x + v[i].y + v[i].z + v[i].w;
        s2 += v[i].x * v[i].x + v[i].y * v[i].y + v[i].z * v[i].z + v[i].w * v[i].w;
    }
#pragma unroll
    for (int o = 16; o > 0; o >>= 1) {
        s  += __shfl_xor_sync(0xffffffffu, s,  o);
        s2 += __shfl_xor_sync(0xffffffffu, s2, o);
    }
    float mu  = s * (1.0f / CDIM);
    float var = s2 * (1.0f / CDIM) - mu * mu;
    float r = rsqrtf(var + 1e-6f);

    __half* op = xout + (size_t)t * CDIM;
#pragma unroll
    for (int i = 0; i < 3; ++i) {
        int idx = (lane + 32 * i) * 4;
        float4 g = *(const float4*)(sc + idx);
        float4 b4 = *(const float4*)(bi + idx);
        uint2 pk;
        pk.x = pack_h2((v[i].x - mu) * r * g.x + b4.x, (v[i].y - mu) * r * g.y + b4.y);
        pk.y = pack_h2((v[i].z - mu) * r * g.z + b4.z, (v[i].w - mu) * r * g.w + b4.w);
        *(uint2*)(op + idx) = pk;
    }
}

// ---------------- LN2: fp16 input (x2), no remap -> fp16 ------------------------
__global__ void __launch_bounds__(256)
ln2_kernel(const __half* __restrict__ xin,
           const float* __restrict__ sc,
           const float* __restrict__ bi,
           __half* __restrict__ xout) {
    int t = blockIdx.x * 8 + (threadIdx.x >> 5);
    int lane = threadIdx.x & 31;

    const uint2* xp = (const uint2*)(xin + (size_t)t * CDIM);  // 4 halves per uint2
    float v[12];
    float s = 0.f, s2 = 0.f;
#pragma unroll
    for (int i = 0; i < 3; ++i) {
        uint2 u = xp[lane + 32 * i];
        float2 a = __half22float2(*(__half2*)&u.x);
        float2 b = __half22float2(*(__half2*)&u.y);
        v[4 * i] = a.x; v[4 * i + 1] = a.y; v[4 * i + 2] = b.x; v[4 * i + 3] = b.y;
        s  += a.x + a.y + b.x + b.y;
        s2 += a.x * a.x + a.y * a.y + b.x * b.x + b.y * b.y;
    }
#pragma unroll
    for (int o = 16; o > 0; o >>= 1) {
        s  += __shfl_xor_sync(0xffffffffu, s,  o);
        s2 += __shfl_xor_sync(0xffffffffu, s2, o);
    }
    float mu  = s * (1.0f / CDIM);
    float var = s2 * (1.0f / CDIM) - mu * mu;
    float r = rsqrtf(var + 1e-6f);

    __half* op = xout + (size_t)t * CDIM;
#pragma unroll
    for (int i = 0; i < 3; ++i) {
        int idx = (lane + 32 * i) * 4;
        float4 g = *(const float4*)(sc + idx);
        float4 b4 = *(const float4*)(bi + idx);
        uint2 pk;
        pk.x = pack_h2((v[4 * i] - mu) * r * g.x + b4.x, (v[4 * i + 1] - mu) * r * g.y + b4.y);
        pk.y = pack_h2((v[4 * i + 2] - mu) * r * g.z + b4.z, (v[4 * i + 3] - mu) * r * g.w + b4.w);
        *(uint2*)(op + idx) = pk;
    }
}

// ---------------- HMMA windowed attention (R14/15-measured structure) -----------
__global__ void __launch_bounds__(128)
attn_mma(const __half* __restrict__ qkv, __half* __restrict__ out) {
    int blk = blockIdx.x;
    int win = blk / NHEAD, head = blk - win * NHEAD;
    int wy = (win >> 3) & 7, wx = win & 7;

    __shared__ __align__(16) __half Ks[64 * 40];
    __shared__ __align__(16) __half Vs[64 * 40];
    __shared__ int rg[64];

    const int tid = threadIdx.x;
    const int lane = tid & 31, warp = tid >> 5;
    const __half* base  = qkv + (size_t)win * NPOS * (3 * CDIM);
    const __half* qhead = base + head * DHEAD;

#pragma unroll
    for (int i = tid; i < 15 * 20; i += 128) {
        int r = 49 + i / 20, c = i % 20;
        ((float*)Ks)[r * 20 + c] = 0.f;
        ((float*)Vs)[r * 20 + c] = 0.f;
    }
    for (int u = tid; u < 196; u += 128) {
        int r = u >> 2, cc = u & 3;
        const __half* rp = base + (size_t)r * (3 * CDIM) + head * DHEAD + cc * 8;
        *(uint4*)(Ks + r * 40 + cc * 8) = *(const uint4*)(rp + CDIM);
        *(uint4*)(Vs + r * 40 + cc * 8) = *(const uint4*)(rp + 2 * CDIM);
    }
    for (int p = tid; p < NPOS; p += 128) {
        int py = p / 7, px = p - py * 7;
        int hy = wy * 7 + py, hx = wx * 7 + px;
        int cy = hy < 49 ? 0 : (hy < 53 ? 1 : 2);
        int cx = hx < 49 ? 0 : (hx < 53 ? 1 : 2);
        rg[p] = cy * 3 + cx;
    }
    __syncthreads();

    const uint32_t kb = smem_u32(Ks), vb = smem_u32(Vs);
    const float scale = 0.17677669529663687f;

    int  rk[7][2];
    bool kv_ok[7][2];
#pragma unroll
    for (int nt = 0; nt < 7; ++nt)
#pragma unroll
        for (int c = 0; c < 2; ++c) {
            int k = 8 * nt + 2 * (lane & 3) + c;
            kv_ok[nt][c] = (k < 49);
            rk[nt][c] = rg[k < 49 ? k : 0];
        }

    const int mt = warp;
    int r0 = mt * 16 + (lane >> 2), r1 = r0 + 8;
    bool ok0 = r0 < NPOS, ok1 = r1 < NPOS;
    const __half* q0p = qhead + (size_t)r0 * (3 * CDIM);
    const __half* q1p = qhead + (size_t)r1 * (3 * CDIM);
    uint32_t afr[2][4];
#pragma unroll
    for (int kk = 0; kk < 2; ++kk) {
        int c0 = kk * 16 + (lane & 3) * 2, c1 = c0 + 8;
        afr[kk][0] = ok0 ? *(const uint32_t*)(q0p + c0) : 0u;
        afr[kk][1] = ok1 ? *(const uint32_t*)(q1p + c0) : 0u;
        afr[kk][2] = ok0 ? *(const uint32_t*)(q0p + c1) : 0u;
        afr[kk][3] = ok1 ? *(const uint32_t*)(q1p + c1) : 0u;
    }

    float sc[7][4];
#pragma unroll
    for (int nt = 0; nt < 7; ++nt)
#pragma unroll
        for (int r = 0; r < 4; ++r) sc[nt][r] = 0.f;

#pragma unroll
    for (int kk = 0; kk < 2; ++kk) {
#pragma unroll
        for (int np = 0; np < 4; ++np) {
            uint32_t t[4];
            ldsm4(t, kb + (np * 16 + (lane & 15)) * 80 + (lane >> 4) * 16 + kk * 32);
            uint32_t b0[2] = {t[0], t[2]};
            uint32_t b1[2] = {t[1], t[3]};
            mma_h32(sc[2 * np], afr[kk], b0);
            if (2 * np + 1 < 7) mma_h32(sc[2 * np + 1], afr[kk], b1);
        }
    }

    int rq0 = ok0 ? rg[r0] : -1;
    int rq1 = ok1 ? rg[r1] : -1;
    float mx0 = -1e30f, mx1 = -1e30f;
#pragma unroll
    for (int nt = 0; nt < 7; ++nt) {
#pragma unroll
        for (int r = 0; r < 4; ++r) {
            int half_ = r >> 1, c = r & 1;
            float s = sc[nt][r] * scale;
            if (!kv_ok[nt][c]) s = -1e30f;
            else if (rk[nt][c] != (half_ ? rq1 : rq0)) s -= 100.f;
            sc[nt][r] = s;
            if (half_ == 0) mx0 = fmaxf(mx0, s); else mx1 = fmaxf(mx1, s);
        }
    }
    mx0 = fmaxf(mx0, __shfl_xor_sync(~0u, mx0, 1));
    mx0 = fmaxf(mx0, __shfl_xor_sync(~0u, mx0, 2));
    mx1 = fmaxf(mx1, __shfl_xor_sync(~0u, mx1, 1));
    mx1 = fmaxf(mx1, __shfl_xor_sync(~0u, mx1, 2));
    float s0 = 0.f, s1 = 0.f;
    uint32_t pk[7][2];
#pragma unroll
    for (int nt = 0; nt < 7; ++nt) {
        float e0 = __expf(sc[nt][0] - mx0); s0 += e0;
        float e1 = __expf(sc[nt][1] - mx0); s0 += e1;
        float e2 = __expf(sc[nt][2] - mx1); s1 += e2;
        float e3 = __expf(sc[nt][3] - mx1); s1 += e3;
        pk[nt][0] = pack_h2(e0, e1);
        pk[nt][1] = pack_h2(e2, e3);
    }
    s0 += __shfl_xor_sync(~0u, s0, 1); s0 += __shfl_xor_sync(~0u, s0, 2);
    s1 += __shfl_xor_sync(~0u, s1, 1); s1 += __shfl_xor_sync(~0u, s1, 2);
    float inv0 = 1.f / s0, inv1 = 1.f / s1;

    float acc[4][4];
#pragma unroll
    for (int nt = 0; nt < 4; ++nt)
#pragma unroll
        for (int r = 0; r < 4; ++r) acc[nt][r] = 0.f;

#pragma unroll
    for (int kt = 0; kt < 4; ++kt) {
        uint32_t vbf[4][2];
#pragma unroll
        for (int np = 0; np < 2; ++np) {
            uint32_t t[4];
            ldsm4t(t, vb + (kt * 16 + (lane & 15)) * 80 + ((lane >> 4) * 8 + np * 16) * 2);
            vbf[2 * np][0] = t[0]; vbf[2 * np][1] = t[1];
            vbf[2 * np + 1][0] = t[2]; vbf[2 * np + 1][1] = t[3];
        }
        uint32_t a[4];
        const int ta = 2 * kt, tb = 2 * kt + 1;
        a[0] = pk[ta][0]; a[1] = pk[ta][1];
        if (tb < 7) { a[2] = pk[tb][0]; a[3] = pk[tb][1]; }
        else        { a[2] = 0u;        a[3] = 0u; }
#pragma unroll
        for (int nt = 0; nt < 4; ++nt) mma_h32(acc[nt], a, vbf[nt]);
    }

#pragma unroll
    for (int half_ = 0; half_ < 2; ++half_) {
        int q = r0 + 8 * half_;
        if (q < NPOS) {
            __half* op = out + ((size_t)win * NPOS + q) * CDIM + head * DHEAD;
            float iv = half_ ? inv1 : inv0;
#pragma unroll
            for (int nt = 0; nt < 4; ++nt) {
                int d = nt * 8 + 2 * (lane & 3);
                *(uint32_t*)(op + d) = pack_h2(
                    acc[nt][2 * half_] * iv, acc[nt][2 * half_ + 1] * iv);
            }
        }
    }
}

// ---------------- HMMA fp16 GEMM, f32 accumulate (R14-measured config) ----------
__device__ __forceinline__ float gelu_tanh(float v) {
    float u = 0.7978845608028654f * (v + 0.044715f * v * v * v);
    return 0.5f * v * (1.0f + tanhf(u));
}

#define ASTG 18432u
#define BSTG 17408u
#define SMEM_GEMM (2u * (ASTG + BSTG))

// EPI 0: +bias -> fp16 (qkv) | 1: gelu(+bias) -> fp16 (mlp1)
// EPI 2: +bias +res(x fp32), scatter -> x2 fp16
// EPI 3: +bias +res(x2 fp16) -> out fp32
template <int EPI>
__global__ __launch_bounds__(256, 2)
void hgemm(const __half* __restrict__ A,
           const __half* __restrict__ Bw,
           const float* __restrict__ bias,
           void* __restrict__ CoutV,
           const void* __restrict__ resV,
           int Nn, int K) {
    extern __shared__ char smraw[];
    const uint32_t a_base = smem_u32(smraw);
    const uint32_t b_base = a_base + 2u * ASTG;

    const int tid = threadIdx.x, lane = tid & 31, warp = tid >> 5;
    const int wm = warp & 3, wn = warp >> 2;
    const int bx = blockIdx.x, by = blockIdx.y;

    const __half* Ag = A  + (size_t)(by * 128) * K;
    const __half* Bg = Bw + bx * 128;

    auto load_stage = [&](int buf, int k0) {
        uint32_t a_s = a_base + buf * ASTG;
        uint32_t b_s = b_base + buf * BSTG;
#pragma unroll
        for (int j = 0; j < 4; ++j) {
            int id = tid + j * 256;
            int row = id >> 3, cc = id & 7;
            cp16(a_s + row * 144 + cc * 16, Ag + (size_t)row * K + k0 + cc * 8);
        }
#pragma unroll
        for (int j = 0; j < 4; ++j) {
            int id = tid + j * 256;
            int row = id >> 4, cc = id & 15;
            cp16(b_s + row * 272 + cc * 16, Bg + (size_t)(k0 + row) * Nn + cc * 8);
        }
        CP_COMMIT();
    };

    float acc[2][8][4];
#pragma unroll
    for (int i = 0; i < 2; ++i)
#pragma unroll
        for (int j = 0; j < 8; ++j)
#pragma unroll
            for (int q = 0; q < 4; ++q) acc[i][j][q] = 0.f;

    const int kIters = K >> 6;
    load_stage(0, 0);

    const uint32_t a_lm = a_base + (wm * 32 + (lane & 15)) * 144 + (lane >> 4) * 16;
    const uint32_t b_lm = b_base + (lane & 15) * 272 + (wn * 64 + (lane >> 4) * 8) * 2;

    for (int i = 0; i < kIters; ++i) {
        int cur = i & 1;
        if (i + 1 < kIters) { load_stage(1 - cur, (i + 1) * 64); CP_WAIT(1); }
        else CP_WAIT(0);
        __syncthreads();

        uint32_t aS = a_lm + cur * ASTG;
        uint32_t bS = b_lm + cur * BSTG;
#pragma unroll
        for (int kk = 0; kk < 4; ++kk) {
            uint32_t a[2][4];
#pragma unroll
            for (int mi = 0; mi < 2; ++mi)
                ldsm4(a[mi], aS + mi * 16 * 144 + kk * 32);
            uint32_t b[8][2];
#pragma unroll
            for (int nq = 0; nq < 4; ++nq) {
                uint32_t t[4];
                ldsm4t(t, bS + kk * 16 * 272 + nq * 32);
                b[2 * nq][0] = t[0]; b[2 * nq][1] = t[1];
                b[2 * nq + 1][0] = t[2]; b[2 * nq + 1][1] = t[3];
            }
#pragma unroll
            for (int mi = 0; mi < 2; ++mi)
#pragma unroll
                for (int ni = 0; ni < 8; ++ni)
                    mma_h32(acc[mi][ni], a[mi], b[ni]);
        }
        __syncthreads();
    }

    const int gid = lane >> 2, tig2 = (lane & 3) * 2;
#pragma unroll
    for (int mi = 0; mi < 2; ++mi) {
#pragma unroll
        for (int hf = 0; hf < 2; ++hf) {
            int m = by * 128 + wm * 32 + mi * 16 + gid + hf * 8;
            size_t orow_off;
            if (EPI == 2) {
                int win = m / NPOS, npos = m - win * NPOS;
                int b = win >> 6, wy = (win >> 3) & 7, wx = win & 7;
                int py = npos / 7, px = npos - py * 7;
                int yy = wy * 7 + py + 3; if (yy >= 56) yy -= 56;
                int xx = wx * 7 + px + 3; if (xx >= 56) xx -= 56;
                orow_off = ((size_t)b * 3136 + yy * 56 + xx) * (size_t)Nn;
            } else {
                orow_off = (size_t)m * Nn;
            }
#pragma unroll
            for (int ni = 0; ni < 8; ++ni) {
                int n = bx * 128 + wn * 64 + ni * 8 + tig2;
                float v0 = acc[mi][ni][hf * 2 + 0] + bias[n];
                float v1 = acc[mi][ni][hf * 2 + 1] + bias[n + 1];
                if (EPI == 1) { v0 = gelu_tanh(v0); v1 = gelu_tanh(v1); }
                if (EPI == 0 || EPI == 1) {
                    *(uint32_t*)((__half*)CoutV + orow_off + n) = pack_h2(v0, v1);
                } else if (EPI == 2) {
                    // residual x is fp32; output x2 is fp16
                    float2 rr = *(const float2*)((const float*)resV + orow_off + n);
                    *(uint32_t*)((__half*)CoutV + orow_off + n) =
                        pack_h2(v0 + rr.x, v1 + rr.y);
                } else {
                    // residual x2 is fp16; output is fp32
                    uint32_t ru = *(const uint32_t*)((const __half*)resV + orow_off + n);
                    float2 rr = __half22float2(*(__half2*)&ru);
                    *(float2*)((float*)CoutV + orow_off + n) =
                        make_float2(v0 + rr.x, v1 + rr.y);
                }
            }
        }
    }
}

// ---------------- launch ----------------------------------------------------------
extern "C" void kernel_launch(void* const* d_in, const int* in_sizes, int n_in,
                              void* d_out, int out_size) {
    const float* x     = (const float*)d_in[0];
    const float* n1s   = (const float*)d_in[1];
    const float* n1b   = (const float*)d_in[2];
    const float* qkvw  = (const float*)d_in[3];
    const float* qkvb  = (const float*)d_in[4];
    const float* projw = (const float*)d_in[5];
    const float* projb = (const float*)d_in[6];
    const float* n2s   = (const float*)d_in[7];
    const float* n2b   = (const float*)d_in[8];
    const float* w1    = (const float*)d_in[9];
    const float* b1    = (const float*)d_in[10];
    const float* w2    = (const float*)d_in[11];
    const float* b2    = (const float*)d_in[12];
    float* out = (float*)d_out;

    __half *xw, *qkv, *att, *x2, *xn2, *h1, *wqkv, *wproj, *wm1, *wm2;
    cudaGetSymbolAddress((void**)&xw,   g_xw);
    cudaGetSymbolAddress((void**)&qkv,  g_qkv);
    cudaGetSymbolAddress((void**)&att,  g_att);
    cudaGetSymbolAddress((void**)&x2,   g_x2);
    cudaGetSymbolAddress((void**)&xn2,  g_xn2);
    cudaGetSymbolAddress((void**)&h1,   g_h1);
    cudaGetSymbolAddress((void**)&wqkv, g_wqkv);
    cudaGetSymbolAddress((void**)&wproj,g_wproj);
    cudaGetSymbolAddress((void**)&wm1,  g_wm1);
    cudaGetSymbolAddress((void**)&wm2,  g_wm2);

    static bool attr_done = false;
    if (!attr_done) {
        cudaFuncSetAttribute(hgemm<0>, cudaFuncAttributeMaxDynamicSharedMemorySize, SMEM_GEMM);
        cudaFuncSetAttribute(hgemm<1>, cudaFuncAttributeMaxDynamicSharedMemorySize, SMEM_GEMM);
        cudaFuncSetAttribute(hgemm<2>, cudaFuncAttributeMaxDynamicSharedMemorySize, SMEM_GEMM);
        cudaFuncSetAttribute(hgemm<3>, cudaFuncAttributeMaxDynamicSharedMemorySize, SMEM_GEMM);
        attr_done = true;
    }

    const int wtot = WS0 + WS1 + WS2 + WS3;
    wconv_all<<<(wtot + 255) / 256, 256>>>(qkvw, projw, w1, w2, wqkv, wproj, wm1, wm2);

    ln1_kernel<<<TOK / 8, 256>>>(x, n1s, n1b, xw);
    hgemm<0><<<dim3(1152 / 128, TOK / 128), 256, SMEM_GEMM>>>(xw, wqkv, qkvb, qkv, nullptr, 1152, CDIM);
    attn_mma<<<NWIN * NHEAD, 128>>>(qkv, att);
    hgemm<2><<<dim3(CDIM / 128, TOK / 128), 256, SMEM_GEMM>>>(att, wproj, projb, x2, x, CDIM, CDIM);
    ln2_kernel<<<TOK / 8, 256>>>(x2, n2s, n2b, xn2);
    hgemm<1><<<dim3(HID / 128, TOK / 128), 256, SMEM_GEMM>>>(xn2, wm1, b1, h1, nullptr, HID, CDIM);
    hgemm<3><<<dim3(CDIM / 128, TOK / 128), 256, SMEM_GEMM>>>(h1, wm2, b2, out, x2, CDIM, HID);
}